// round 11
// baseline (speedup 1.0000x reference)
#include <cuda_runtime.h>
#include <cuda_fp16.h>
#include <cstdint>
#include <cstddef>

// ============================================================================
// GCN layer: out = relu(dinv_m * (A @ (dinv_k * (X W^T)))), A 8192x8192 fp32.
// PTX target is plain sm_100 (no tcgen05) -> mma.sync.m16n8k16.f16 (10-bit
// mantissa like tf32, fp32 accumulate, half the MMA instructions of tf32).
// A is converted fp32->fp16 INLINE in the GEMM load path (no 128 MB scratch).
// R11: 3-deep A-LDG register ring, STS after MMA block, evict_first via
// 256-bit v8.b32 loads (ptxas requires v8.b32/v4.b64 with L2::evict_first).
// ============================================================================

static constexpr int N_NODES = 8192;
static constexpr int D_FEAT  = 128;

__device__ __align__(128) float  g_dinv[N_NODES];
__device__ __align__(128) __half g_Gh[(size_t)D_FEAT * N_NODES];  // 2 MB, [o][k]

__device__ __forceinline__ uint32_t h2_as_u32(__half2 h) {
    return *reinterpret_cast<uint32_t*>(&h);
}

// ============================================================================
// K1: deg row sums -> dinv = rsqrt(deg). Pure 268 MB DRAM stream (42 us).
// ============================================================================

__global__ __launch_bounds__(128) void deg_kernel(const float* __restrict__ A) {
    __shared__ float red[4];
    const int row = blockIdx.x;
    const int t = threadIdx.x;
    const float4* a4 = reinterpret_cast<const float4*>(A + (size_t)row * N_NODES);
    float s0 = 0.f, s1 = 0.f, s2 = 0.f, s3 = 0.f;
    #pragma unroll
    for (int i = 0; i < 4; i++) {
        float4 v0 = a4[t + (4 * i + 0) * 128];
        float4 v1 = a4[t + (4 * i + 1) * 128];
        float4 v2 = a4[t + (4 * i + 2) * 128];
        float4 v3 = a4[t + (4 * i + 3) * 128];
        s0 += v0.x + v0.y + v0.z + v0.w;
        s1 += v1.x + v1.y + v1.z + v1.w;
        s2 += v2.x + v2.y + v2.z + v2.w;
        s3 += v3.x + v3.y + v3.z + v3.w;
    }
    float s = (s0 + s1) + (s2 + s3);
    #pragma unroll
    for (int off = 16; off > 0; off >>= 1)
        s += __shfl_xor_sync(0xFFFFFFFFu, s, off);
    if ((t & 31) == 0) red[t >> 5] = s;
    __syncthreads();
    if (t == 0) {
        float total = (red[0] + red[1]) + (red[2] + red[3]);
        g_dinv[row] = rsqrtf(total);
    }
}

// ============================================================================
// K2: Gh[o][k] = fp16( dinv[k] * sum_d X[k][d] * W[o][d] )
// ============================================================================

static constexpr int K2_ROWS = 32;
static constexpr int W_PAD   = 132;
static constexpr int K2_SMEM = (128 * W_PAD + 128) * 4;

__global__ __launch_bounds__(128) void build_gt(const float* __restrict__ X,
                                                const float* __restrict__ W) {
    extern __shared__ __align__(16) float k2sm[];
    float* Ws = k2sm;                 // [128][W_PAD]
    float* Xs = k2sm + 128 * W_PAD;   // [128]

    for (int idx = threadIdx.x; idx < 128 * 128; idx += 128) {
        int o = idx >> 7, d = idx & 127;
        Ws[o * W_PAD + d] = W[idx];
    }
    __syncthreads();

    const int k0 = blockIdx.x * K2_ROWS;
    const int o = threadIdx.x;
    const float4* Wrow = reinterpret_cast<const float4*>(Ws + o * W_PAD);

    for (int kk = 0; kk < K2_ROWS; kk++) {
        const int k = k0 + kk;
        Xs[o] = X[(size_t)k * 128 + o];
        __syncthreads();
        const float4* X4 = reinterpret_cast<const float4*>(Xs);
        float acc = 0.f;
        #pragma unroll
        for (int q = 0; q < 32; q++) {
            float4 w = Wrow[q];
            float4 x = X4[q];
            acc += w.x * x.x + w.y * x.y + w.z * x.z + w.w * x.w;
        }
        g_Gh[(size_t)o * N_NODES + k] = __float2half_rn(acc * g_dinv[k]);
        __syncthreads();
    }
}

// ============================================================================
// K3: fp16 mma.sync GEMM + fused epilogue.
//   out[m][o] = relu(dinv[m] * sum_k fp16(A[m][k]) * Gh[o][k])
// CTA tile 64x128, KC=64, 4-stage smem ring. A: 256-bit LDG (evict_first) ->
// cvt -> STS fp16, 3-iter register prefetch ring, STS placed AFTER the MMA
// block. B: cp.async (g_Gh stays L2-resident thanks to A's evict_first).
// 512 threads (16 warps, warp tile 32x16), ldmatrix.x4 fragment loads.
// Rows padded to 72 halves (144 B): all ldmatrix/STS phases conflict-free.
// ============================================================================

static constexpr int TILE_M = 64;
static constexpr int TILE_N = 128;
static constexpr int KC     = 64;
static constexpr int STAGES = 4;
static constexpr int ITERS  = N_NODES / KC;                    // 128
static constexpr int ROWF   = 72;
static constexpr int ROWB   = ROWF * 2;                        // 144 B
static constexpr uint32_t A_STAGE_B = TILE_M * ROWB;           // 9216
static constexpr uint32_t B_STAGE_B = TILE_N * ROWB;           // 18432
static constexpr uint32_t STAGE_B   = A_STAGE_B + B_STAGE_B;   // 27648
static constexpr uint32_t GEMM_SMEM = STAGES * STAGE_B;        // 110592
static constexpr int NTHR    = 512;
static constexpr int B_CHUNKS = TILE_N * (KC * 2 / 16);        // 1024
static constexpr int B_CPT    = B_CHUNKS / NTHR;               // 2

__device__ __forceinline__ uint32_t smem_to_u32(const void* p) {
    uint32_t a;
    asm("{ .reg .u64 t; cvta.to.shared.u64 t, %1; cvt.u32.u64 %0, t; }"
        : "=r"(a) : "l"(p));
    return a;
}

__device__ __forceinline__ void ldsm_x4(uint32_t r[4], uint32_t addr) {
    asm volatile("ldmatrix.sync.aligned.m8n8.x4.shared.b16 {%0,%1,%2,%3}, [%4];"
                 : "=r"(r[0]), "=r"(r[1]), "=r"(r[2]), "=r"(r[3]) : "r"(addr));
}

__device__ __forceinline__ void mma_f16(float d[4], const uint32_t a[4],
                                        uint32_t b0, uint32_t b1) {
    asm volatile(
        "mma.sync.aligned.m16n8k16.row.col.f32.f16.f16.f32 "
        "{%0,%1,%2,%3}, {%4,%5,%6,%7}, {%8,%9}, {%0,%1,%2,%3};"
        : "+f"(d[0]), "+f"(d[1]), "+f"(d[2]), "+f"(d[3])
        : "r"(a[0]), "r"(a[1]), "r"(a[2]), "r"(a[3]), "r"(b0), "r"(b1));
}

// A load: 32 B (8 floats) per instruction, L2 evict_first (A is stream-once;
// protect G's L2 residency, which all 128 CTAs re-read). ptxas requires
// v8.b32 width for the evict_first modifier on this target.
__device__ __forceinline__ void ldg_ef8(const float* p, float v[8]) {
    asm volatile(
        "ld.global.nc.L2::evict_first.v8.b32 {%0,%1,%2,%3,%4,%5,%6,%7}, [%8];"
        : "=f"(v[0]), "=f"(v[1]), "=f"(v[2]), "=f"(v[3]),
          "=f"(v[4]), "=f"(v[5]), "=f"(v[6]), "=f"(v[7])
        : "l"(p));
}

__global__ __launch_bounds__(NTHR, 1) void gcn_gemm(const float* __restrict__ A,
                                                    float* __restrict__ out) {
    extern __shared__ __align__(16) char smem_c[];
    const int tid = threadIdx.x;
    const int lane = tid & 31;
    const int wid = tid >> 5;
    const int warp_m = wid & 1;        // 2 warp rows of 32
    const int warp_n = wid >> 1;       // 8 warp cols of 16
    const int m0 = blockIdx.x * TILE_M;
    const uint32_t sbase = smem_to_u32(smem_c);

    // ---- A load plan: thread -> (row = tid/8, seg = tid%8), 8 floats each
    const int a_row = tid >> 3;
    const int a_seg = tid & 7;
    const float* a_src = A + (size_t)(m0 + a_row) * N_NODES + a_seg * 8;
    const uint32_t a_sts = sbase + (uint32_t)(a_row * ROWB + a_seg * 16);

    // ---- B cp.async plan: 2 x 16B per thread per stage
    const char* b_srcs[B_CPT];
    uint32_t b_dsts[B_CPT];
    #pragma unroll
    for (int u = 0; u < B_CPT; u++) {
        int id = tid + u * NTHR;
        int row = id >> 3, c = id & 7;
        b_dsts[u] = A_STAGE_B + (uint32_t)(row * ROWB + c * 16);
        b_srcs[u] = (const char*)(g_Gh + (size_t)row * N_NODES) + c * 16;
    }

    auto issueB = [&](int j) {
        const uint32_t st = sbase + (uint32_t)(j % STAGES) * STAGE_B;
        const size_t koff = (size_t)j * (KC * 2);
        #pragma unroll
        for (int u = 0; u < B_CPT; u++) {
            asm volatile("cp.async.cg.shared.global [%0], [%1], 16;"
                         :: "r"(st + b_dsts[u]), "l"(b_srcs[u] + koff) : "memory");
        }
    };
    auto ldgA = [&](int j, float r[8]) {
        ldg_ef8(a_src + (size_t)j * KC, r);
    };
    auto stsA = [&](int j, const float r[8]) {
        uint32_t h0 = h2_as_u32(__floats2half2_rn(r[0], r[1]));
        uint32_t h1 = h2_as_u32(__floats2half2_rn(r[2], r[3]));
        uint32_t h2 = h2_as_u32(__floats2half2_rn(r[4], r[5]));
        uint32_t h3 = h2_as_u32(__floats2half2_rn(r[6], r[7]));
        const uint32_t ad = a_sts + (uint32_t)(j % STAGES) * STAGE_B;
        asm volatile("st.shared.v4.b32 [%0], {%1,%2,%3,%4};"
                     :: "r"(ad), "r"(h0), "r"(h1), "r"(h2), "r"(h3) : "memory");
    };

    // ---- prologue: 3-deep A register ring + 3 B stages in flight
    float regA[3][8];
    ldgA(0, regA[0]);
    ldgA(1, regA[1]);
    ldgA(2, regA[2]);
    issueB(0); asm volatile("cp.async.commit_group;" ::: "memory");
    issueB(1); asm volatile("cp.async.commit_group;" ::: "memory");
    issueB(2); asm volatile("cp.async.commit_group;" ::: "memory");
    stsA(0, regA[0]);

    // ---- ldmatrix lane addressing (bytes, within stage)
    const uint32_t a_off = (uint32_t)((warp_m * 32 + (lane & 15)) * ROWB
                                      + ((lane >> 4) * 8) * 2);
    const uint32_t b_off = A_STAGE_B
        + (uint32_t)((warp_n * 16 + ((lane >> 4) << 3) + (lane & 7)) * ROWB
                     + (((lane >> 3) & 1) * 8) * 2);

    float acc[2][2][4];
    #pragma unroll
    for (int mf = 0; mf < 2; mf++)
        #pragma unroll
        for (int nf = 0; nf < 2; nf++)
            #pragma unroll
            for (int q = 0; q < 4; q++) acc[mf][nf][q] = 0.f;

    for (int i = 0; i < ITERS; i++) {
        asm volatile("cp.async.wait_group %0;" :: "n"(STAGES - 2) : "memory");
        __syncthreads();   // B(i) arrived; A(i) STS visible

        if (i + 3 < ITERS) issueB(i + 3);
        asm volatile("cp.async.commit_group;" ::: "memory");
        if (i + 3 < ITERS) ldgA(i + 3, regA[i % 3]);   // slot i%3 freed last iter

        const uint32_t st = sbase + (uint32_t)(i % STAGES) * STAGE_B;
        const uint32_t aA = st + a_off;
        const uint32_t aB = st + b_off;
        #pragma unroll
        for (int kk = 0; kk < KC / 16; kk++) {
            const uint32_t ko = (uint32_t)(kk * 32);   // 16 halves = 32 B
            uint32_t af0[4], af1[4], bf[4];
            ldsm_x4(af0, aA + ko);
            ldsm_x4(af1, aA + 16 * ROWB + ko);
            ldsm_x4(bf, aB + ko);
            mma_f16(acc[0][0], af0, bf[0], bf[1]);
            mma_f16(acc[0][1], af0, bf[2], bf[3]);
            mma_f16(acc[1][0], af1, bf[0], bf[1]);
            mma_f16(acc[1][1], af1, bf[2], bf[3]);
        }

        // A-store for the NEXT stage, after tensor work (LDG from iter i-2
        // has had ~2 full iterations to land).
        if (i + 1 < ITERS) stsA(i + 1, regA[(i + 1) % 3]);
    }

    // ---- fused epilogue: dinv_m scale + relu -> d_out
    const int qr = lane >> 2;
    const int qc = lane & 3;
    #pragma unroll
    for (int mf = 0; mf < 2; mf++) {
        const int m = m0 + warp_m * 32 + mf * 16 + qr;
        const float d0 = g_dinv[m];
        const float d1 = g_dinv[m + 8];
        #pragma unroll
        for (int nf = 0; nf < 2; nf++) {
            const int n = warp_n * 16 + nf * 8 + 2 * qc;
            float2 v0, v1;
            v0.x = fmaxf(d0 * acc[mf][nf][0], 0.f);
            v0.y = fmaxf(d0 * acc[mf][nf][1], 0.f);
            v1.x = fmaxf(d1 * acc[mf][nf][2], 0.f);
            v1.y = fmaxf(d1 * acc[mf][nf][3], 0.f);
            *reinterpret_cast<float2*>(out + (size_t)m * D_FEAT + n) = v0;
            *reinterpret_cast<float2*>(out + (size_t)(m + 8) * D_FEAT + n) = v1;
        }
    }
}

// ============================================================================
// Launch
// ============================================================================

extern "C" void kernel_launch(void* const* d_in, const int* in_sizes, int n_in,
                              void* d_out, int out_size) {
    const float* A = (const float*)d_in[0];
    const float* X = (const float*)d_in[1];
    const float* W = (const float*)d_in[2];
    for (int i = 0; i < n_in; i++) {
        if (in_sizes[i] == N_NODES * N_NODES)      A = (const float*)d_in[i];
        else if (in_sizes[i] == N_NODES * D_FEAT)  X = (const float*)d_in[i];
        else if (in_sizes[i] == D_FEAT * D_FEAT)   W = (const float*)d_in[i];
    }
    float* out = (float*)d_out;

    cudaFuncSetAttribute(build_gt, cudaFuncAttributeMaxDynamicSharedMemorySize,
                         K2_SMEM);
    cudaFuncSetAttribute(gcn_gemm, cudaFuncAttributeMaxDynamicSharedMemorySize,
                         GEMM_SMEM);

    deg_kernel<<<N_NODES, 128>>>(A);
    build_gt<<<N_NODES / K2_ROWS, 128, K2_SMEM>>>(X, W);
    gcn_gemm<<<N_NODES / TILE_M, NTHR, GEMM_SMEM>>>(A, out);
}

// round 14
// speedup vs baseline: 1.2177x; 1.2177x over previous
#include <cuda_runtime.h>
#include <cuda_fp16.h>
#include <cstdint>
#include <cstddef>

// ============================================================================
// GCN layer: out = relu(dinv_m * (A @ (dinv_k * (X W^T)))), A 8192x8192 fp32.
// PTX target is plain sm_100 (no tcgen05) -> mma.sync.m16n8k16.f16.
// R14: NO large device scratch (kernels with the 128 MB g_Ah static are 0/4
// on container bring-up). A streams in fp32 via deep cp.async pipeline and is
// converted to fp16 through a smem-staged pass each iteration (LDS->cvt->STS,
// ~30 cyc latency, zero register-ring pressure). Hot loop has no LDG.
// ============================================================================

static constexpr int N_NODES = 8192;
static constexpr int D_FEAT  = 128;

__device__ __align__(128) float  g_dinv[N_NODES];
__device__ __align__(128) __half g_Gh[(size_t)D_FEAT * N_NODES];  // 2 MB, [o][k]

// ============================================================================
// K1: deg row sums -> dinv = rsqrt(deg). Pure 268 MB DRAM stream (42 us).
// ============================================================================

__global__ __launch_bounds__(128) void deg_kernel(const float* __restrict__ A) {
    __shared__ float red[4];
    const int row = blockIdx.x;
    const int t = threadIdx.x;
    const float4* a4 = reinterpret_cast<const float4*>(A + (size_t)row * N_NODES);
    float s0 = 0.f, s1 = 0.f, s2 = 0.f, s3 = 0.f;
    #pragma unroll
    for (int i = 0; i < 4; i++) {
        float4 v0 = a4[t + (4 * i + 0) * 128];
        float4 v1 = a4[t + (4 * i + 1) * 128];
        float4 v2 = a4[t + (4 * i + 2) * 128];
        float4 v3 = a4[t + (4 * i + 3) * 128];
        s0 += v0.x + v0.y + v0.z + v0.w;
        s1 += v1.x + v1.y + v1.z + v1.w;
        s2 += v2.x + v2.y + v2.z + v2.w;
        s3 += v3.x + v3.y + v3.z + v3.w;
    }
    float s = (s0 + s1) + (s2 + s3);
    #pragma unroll
    for (int off = 16; off > 0; off >>= 1)
        s += __shfl_xor_sync(0xFFFFFFFFu, s, off);
    if ((t & 31) == 0) red[t >> 5] = s;
    __syncthreads();
    if (t == 0) {
        float total = (red[0] + red[1]) + (red[2] + red[3]);
        g_dinv[row] = rsqrtf(total);
    }
}

// ============================================================================
// K2: Gh[o][k] = fp16( dinv[k] * sum_d X[k][d] * W[o][d] )
// ============================================================================

static constexpr int K2_ROWS = 32;
static constexpr int W_PAD   = 132;
static constexpr int K2_SMEM = (128 * W_PAD + 128) * 4;

__global__ __launch_bounds__(128) void build_gt(const float* __restrict__ X,
                                                const float* __restrict__ W) {
    extern __shared__ __align__(16) float k2sm[];
    float* Ws = k2sm;                 // [128][W_PAD]
    float* Xs = k2sm + 128 * W_PAD;   // [128]

    for (int idx = threadIdx.x; idx < 128 * 128; idx += 128) {
        int o = idx >> 7, d = idx & 127;
        Ws[o * W_PAD + d] = W[idx];
    }
    __syncthreads();

    const int k0 = blockIdx.x * K2_ROWS;
    const int o = threadIdx.x;
    const float4* Wrow = reinterpret_cast<const float4*>(Ws + o * W_PAD);

    for (int kk = 0; kk < K2_ROWS; kk++) {
        const int k = k0 + kk;
        Xs[o] = X[(size_t)k * 128 + o];
        __syncthreads();
        const float4* X4 = reinterpret_cast<const float4*>(Xs);
        float acc = 0.f;
        #pragma unroll
        for (int q = 0; q < 32; q++) {
            float4 w = Wrow[q];
            float4 x = X4[q];
            acc += w.x * x.x + w.y * x.y + w.z * x.z + w.w * x.w;
        }
        g_Gh[(size_t)o * N_NODES + k] = __float2half_rn(acc * g_dinv[k]);
        __syncthreads();
    }
}

// ============================================================================
// K3: fp16 mma.sync GEMM + fused epilogue, smem-staged A conversion.
//   out[m][o] = relu(dinv[m] * sum_k fp16(A[m][k]) * Gh[o][k])
// CTA tile 64x128, KC=64. A: cp.async fp32 into 4-stage staging ring; each
// iter 512 threads convert the current stage to a 2-deep fp16 tile ring
// (LDS -> cvt -> STS, smem-local). B: cp.async fp16, 4-stage ring.
// 512 threads (16 warps, warp tile 32x16), ldmatrix.x4 fragment loads.
// fp16 tile rows padded to 144 B -> ldmatrix/STS phases conflict-free.
// Fragment/epilogue mapping identical to R7 (validated, rel_err 3.2e-4).
// ============================================================================

static constexpr int TILE_M = 64;
static constexpr int TILE_N = 128;
static constexpr int KC     = 64;
static constexpr int STAGES = 4;        // A32 + B cp.async stages
static constexpr int ITERS  = N_NODES / KC;                    // 128
static constexpr int ROWB   = 144;                             // fp16 row pad
static constexpr uint32_t A32_STAGE = TILE_M * KC * 4;         // 16384
static constexpr uint32_t B_STAGE   = TILE_N * ROWB;           // 18432
static constexpr uint32_t A16_STAGE = TILE_M * ROWB;           // 9216
static constexpr uint32_t OFF_A32 = 0;
static constexpr uint32_t OFF_B   = OFF_A32 + STAGES * A32_STAGE;   // 65536
static constexpr uint32_t OFF_A16 = OFF_B + STAGES * B_STAGE;       // 139264
static constexpr uint32_t GEMM_SMEM = OFF_A16 + 2 * A16_STAGE;      // 157696
static constexpr int NTHR = 512;

__device__ __forceinline__ uint32_t smem_to_u32(const void* p) {
    uint32_t a;
    asm("{ .reg .u64 t; cvta.to.shared.u64 t, %1; cvt.u32.u64 %0, t; }"
        : "=r"(a) : "l"(p));
    return a;
}

__device__ __forceinline__ uint32_t h2_as_u32(__half2 h) {
    return *reinterpret_cast<uint32_t*>(&h);
}

__device__ __forceinline__ void ldsm_x4(uint32_t r[4], uint32_t addr) {
    asm volatile("ldmatrix.sync.aligned.m8n8.x4.shared.b16 {%0,%1,%2,%3}, [%4];"
                 : "=r"(r[0]), "=r"(r[1]), "=r"(r[2]), "=r"(r[3]) : "r"(addr));
}

__device__ __forceinline__ void mma_f16(float d[4], const uint32_t a[4],
                                        uint32_t b0, uint32_t b1) {
    asm volatile(
        "mma.sync.aligned.m16n8k16.row.col.f32.f16.f16.f32 "
        "{%0,%1,%2,%3}, {%4,%5,%6,%7}, {%8,%9}, {%0,%1,%2,%3};"
        : "+f"(d[0]), "+f"(d[1]), "+f"(d[2]), "+f"(d[3])
        : "r"(a[0]), "r"(a[1]), "r"(a[2]), "r"(a[3]), "r"(b0), "r"(b1));
}

__global__ __launch_bounds__(NTHR, 1) void gcn_gemm(const float* __restrict__ A,
                                                    float* __restrict__ out) {
    extern __shared__ __align__(16) char smem_c[];
    const int tid = threadIdx.x;
    const int lane = tid & 31;
    const int wid = tid >> 5;
    const int warp_m = wid & 1;        // 2 warp rows of 32
    const int warp_n = wid >> 1;       // 8 warp cols of 16
    const int m0 = blockIdx.x * TILE_M;
    const uint32_t sbase = smem_to_u32(smem_c);

    // ---- cp.async plan: 2 A32 chunks + 2 B chunks per thread per stage
    // A32: 1024 chunks of 16 B (64 rows x 256 B); B: 1024 chunks (128 x 128 B)
    const int a1 = tid, a2 = tid + NTHR;
    const uint32_t a_dst1 = OFF_A32 + (uint32_t)((a1 >> 4) * 256 + (a1 & 15) * 16);
    const uint32_t a_dst2 = OFF_A32 + (uint32_t)((a2 >> 4) * 256 + (a2 & 15) * 16);
    const char* a_srcb1 = (const char*)(A + (size_t)(m0 + (a1 >> 4)) * N_NODES)
                          + (a1 & 15) * 16;
    const char* a_srcb2 = (const char*)(A + (size_t)(m0 + (a2 >> 4)) * N_NODES)
                          + (a2 & 15) * 16;
    const int b1 = tid, b2 = tid + NTHR;
    const uint32_t b_dst1 = OFF_B + (uint32_t)((b1 >> 3) * ROWB + (b1 & 7) * 16);
    const uint32_t b_dst2 = OFF_B + (uint32_t)((b2 >> 3) * ROWB + (b2 & 7) * 16);
    const char* b_srcb1 = (const char*)(g_Gh + (size_t)(b1 >> 3) * N_NODES)
                          + (b1 & 7) * 16;
    const char* b_srcb2 = (const char*)(g_Gh + (size_t)(b2 >> 3) * N_NODES)
                          + (b2 & 7) * 16;

    auto issue = [&](int j) {
        const uint32_t sa = (uint32_t)(j & (STAGES - 1)) * A32_STAGE;
        const uint32_t sb = (uint32_t)(j & (STAGES - 1)) * B_STAGE;
        const size_t ka = (size_t)j * (KC * 4);   // fp32 bytes per K chunk
        const size_t kb = (size_t)j * (KC * 2);   // fp16 bytes per K chunk
        asm volatile("cp.async.cg.shared.global [%0], [%1], 16;"
                     :: "r"(sbase + sa + a_dst1), "l"(a_srcb1 + ka) : "memory");
        asm volatile("cp.async.cg.shared.global [%0], [%1], 16;"
                     :: "r"(sbase + sa + a_dst2), "l"(a_srcb2 + ka) : "memory");
        asm volatile("cp.async.cg.shared.global [%0], [%1], 16;"
                     :: "r"(sbase + sb + b_dst1), "l"(b_srcb1 + kb) : "memory");
        asm volatile("cp.async.cg.shared.global [%0], [%1], 16;"
                     :: "r"(sbase + sb + b_dst2), "l"(b_srcb2 + kb) : "memory");
    };

    // ---- convert plan: thread -> (row = tid/8, seg = tid%8), 8 floats
    const int c_row = tid >> 3;
    const int c_seg = tid & 7;
    const uint32_t c_src = OFF_A32 + (uint32_t)(c_row * 256 + c_seg * 32);
    const uint32_t c_dst = OFF_A16 + (uint32_t)(c_row * ROWB + c_seg * 16);

    // ---- prologue: 3 stages in flight
    #pragma unroll
    for (int p = 0; p < STAGES - 1; p++) {
        issue(p);
        asm volatile("cp.async.commit_group;" ::: "memory");
    }

    // ---- ldmatrix lane addressing (bytes, within tile)
    const uint32_t a_off = (uint32_t)((warp_m * 32 + (lane & 15)) * ROWB
                                      + ((lane >> 4) * 8) * 2);
    const uint32_t b_off = (uint32_t)((warp_n * 16 + ((lane >> 4) << 3)
                                       + (lane & 7)) * ROWB
                                      + (((lane >> 3) & 1) * 8) * 2);

    float acc[2][2][4];
    #pragma unroll
    for (int mf = 0; mf < 2; mf++)
        #pragma unroll
        for (int nf = 0; nf < 2; nf++)
            #pragma unroll
            for (int q = 0; q < 4; q++) acc[mf][nf][q] = 0.f;

    for (int i = 0; i < ITERS; i++) {
        asm volatile("cp.async.wait_group %0;" :: "n"(STAGES - 2) : "memory");
        __syncthreads();   // stage i (A32 + B) resident

        // convert A32[i%4] -> A16[i%2] (smem-local, ~30 cyc latency)
        {
            const char* src = smem_c + c_src
                              + (uint32_t)(i & (STAGES - 1)) * A32_STAGE;
            float4 v0 = *reinterpret_cast<const float4*>(src);
            float4 v1 = *reinterpret_cast<const float4*>(src + 16);
            uint4 hv;
            hv.x = h2_as_u32(__floats2half2_rn(v0.x, v0.y));
            hv.y = h2_as_u32(__floats2half2_rn(v0.z, v0.w));
            hv.z = h2_as_u32(__floats2half2_rn(v1.x, v1.y));
            hv.w = h2_as_u32(__floats2half2_rn(v1.z, v1.w));
            *reinterpret_cast<uint4*>(smem_c + c_dst
                + (uint32_t)(i & 1) * A16_STAGE) = hv;
        }

        if (i + STAGES - 1 < ITERS) issue(i + STAGES - 1);
        asm volatile("cp.async.commit_group;" ::: "memory");

        __syncthreads();   // A16[i%2] visible to all warps

        const uint32_t aA = sbase + OFF_A16 + (uint32_t)(i & 1) * A16_STAGE
                            + a_off;
        const uint32_t aB = sbase + OFF_B
                            + (uint32_t)(i & (STAGES - 1)) * B_STAGE + b_off;
        #pragma unroll
        for (int kk = 0; kk < KC / 16; kk++) {     // 4 k16 steps
            const uint32_t ko = (uint32_t)(kk * 32);  // 16 halves = 32 B
            uint32_t af0[4], af1[4], bf[4];
            ldsm_x4(af0, aA + ko);                 // mf 0: rows +0
            ldsm_x4(af1, aA + 16 * ROWB + ko);     // mf 1: rows +16
            ldsm_x4(bf, aB + ko);                  // nf 0 (b0,b1), nf 1 (b2,b3)
            mma_f16(acc[0][0], af0, bf[0], bf[1]);
            mma_f16(acc[0][1], af0, bf[2], bf[3]);
            mma_f16(acc[1][0], af1, bf[0], bf[1]);
            mma_f16(acc[1][1], af1, bf[2], bf[3]);
        }
    }

    // ---- fused epilogue: dinv_m scale + relu -> d_out
    const int qr = lane >> 2;
    const int qc = lane & 3;
    #pragma unroll
    for (int mf = 0; mf < 2; mf++) {
        const int m = m0 + warp_m * 32 + mf * 16 + qr;
        const float d0 = g_dinv[m];
        const float d1 = g_dinv[m + 8];
        #pragma unroll
        for (int nf = 0; nf < 2; nf++) {
            const int n = warp_n * 16 + nf * 8 + 2 * qc;
            float2 v0, v1;
            v0.x = fmaxf(d0 * acc[mf][nf][0], 0.f);
            v0.y = fmaxf(d0 * acc[mf][nf][1], 0.f);
            v1.x = fmaxf(d1 * acc[mf][nf][2], 0.f);
            v1.y = fmaxf(d1 * acc[mf][nf][3], 0.f);
            *reinterpret_cast<float2*>(out + (size_t)m * D_FEAT + n) = v0;
            *reinterpret_cast<float2*>(out + (size_t)(m + 8) * D_FEAT + n) = v1;
        }
    }
}

// ============================================================================
// Launch
// ============================================================================

extern "C" void kernel_launch(void* const* d_in, const int* in_sizes, int n_in,
                              void* d_out, int out_size) {
    const float* A = (const float*)d_in[0];
    const float* X = (const float*)d_in[1];
    const float* W = (const float*)d_in[2];
    for (int i = 0; i < n_in; i++) {
        if (in_sizes[i] == N_NODES * N_NODES)      A = (const float*)d_in[i];
        else if (in_sizes[i] == N_NODES * D_FEAT)  X = (const float*)d_in[i];
        else if (in_sizes[i] == D_FEAT * D_FEAT)   W = (const float*)d_in[i];
    }
    float* out = (float*)d_out;

    cudaFuncSetAttribute(build_gt, cudaFuncAttributeMaxDynamicSharedMemorySize,
                         K2_SMEM);
    cudaFuncSetAttribute(gcn_gemm, cudaFuncAttributeMaxDynamicSharedMemorySize,
                         GEMM_SMEM);

    deg_kernel<<<N_NODES, 128>>>(A);
    build_gt<<<N_NODES / K2_ROWS, 128, K2_SMEM>>>(X, W);
    gcn_gemm<<<N_NODES / TILE_M, NTHR, GEMM_SMEM>>>(A, out);
}

// round 15
// speedup vs baseline: 1.2899x; 1.0592x over previous
#include <cuda_runtime.h>
#include <cuda_fp16.h>
#include <cstdint>
#include <cstddef>

// ============================================================================
// GCN layer: out = relu(dinv_m * (A @ (dinv_k * (X W^T)))), A 8192x8192 fp32.
// PTX target plain sm_100 -> mma.sync.m16n8k16.f16.
// R15: CTA tile 128x128 (split-K=2, grid 64x2=128), 8 warps of 64x32 ->
// halves redundant LDSM traffic per FLOP (smem crossbar was the modeled
// binding term in R14). A converted fp32->fp16 via smem staging as in R14.
// ============================================================================

static constexpr int N_NODES = 8192;
static constexpr int D_FEAT  = 128;

__device__ __align__(128) float  g_dinv[N_NODES];
__device__ __align__(128) __half g_Gh[(size_t)D_FEAT * N_NODES];     // 2 MB
__device__ __align__(128) float  g_Cpart[2][(size_t)N_NODES * D_FEAT]; // 8 MB

// ============================================================================
// K1: deg row sums -> dinv = rsqrt(deg). Pure 268 MB DRAM stream (42 us).
// ============================================================================

__global__ __launch_bounds__(128) void deg_kernel(const float* __restrict__ A) {
    __shared__ float red[4];
    const int row = blockIdx.x;
    const int t = threadIdx.x;
    const float4* a4 = reinterpret_cast<const float4*>(A + (size_t)row * N_NODES);
    float s0 = 0.f, s1 = 0.f, s2 = 0.f, s3 = 0.f;
    #pragma unroll
    for (int i = 0; i < 4; i++) {
        float4 v0 = a4[t + (4 * i + 0) * 128];
        float4 v1 = a4[t + (4 * i + 1) * 128];
        float4 v2 = a4[t + (4 * i + 2) * 128];
        float4 v3 = a4[t + (4 * i + 3) * 128];
        s0 += v0.x + v0.y + v0.z + v0.w;
        s1 += v1.x + v1.y + v1.z + v1.w;
        s2 += v2.x + v2.y + v2.z + v2.w;
        s3 += v3.x + v3.y + v3.z + v3.w;
    }
    float s = (s0 + s1) + (s2 + s3);
    #pragma unroll
    for (int off = 16; off > 0; off >>= 1)
        s += __shfl_xor_sync(0xFFFFFFFFu, s, off);
    if ((t & 31) == 0) red[t >> 5] = s;
    __syncthreads();
    if (t == 0) {
        float total = (red[0] + red[1]) + (red[2] + red[3]);
        g_dinv[row] = rsqrtf(total);
    }
}

// ============================================================================
// K2: Gh[o][k] = fp16( dinv[k] * sum_d X[k][d] * W[o][d] )
// ============================================================================

static constexpr int K2_ROWS = 32;
static constexpr int W_PAD   = 132;
static constexpr int K2_SMEM = (128 * W_PAD + 128) * 4;

__global__ __launch_bounds__(128) void build_gt(const float* __restrict__ X,
                                                const float* __restrict__ W) {
    extern __shared__ __align__(16) float k2sm[];
    float* Ws = k2sm;
    float* Xs = k2sm + 128 * W_PAD;

    for (int idx = threadIdx.x; idx < 128 * 128; idx += 128) {
        int o = idx >> 7, d = idx & 127;
        Ws[o * W_PAD + d] = W[idx];
    }
    __syncthreads();

    const int k0 = blockIdx.x * K2_ROWS;
    const int o = threadIdx.x;
    const float4* Wrow = reinterpret_cast<const float4*>(Ws + o * W_PAD);

    for (int kk = 0; kk < K2_ROWS; kk++) {
        const int k = k0 + kk;
        Xs[o] = X[(size_t)k * 128 + o];
        __syncthreads();
        const float4* X4 = reinterpret_cast<const float4*>(Xs);
        float acc = 0.f;
        #pragma unroll
        for (int q = 0; q < 32; q++) {
            float4 w = Wrow[q];
            float4 x = X4[q];
            acc += w.x * x.x + w.y * x.y + w.z * x.z + w.w * x.w;
        }
        g_Gh[(size_t)o * N_NODES + k] = __float2half_rn(acc * g_dinv[k]);
        __syncthreads();
    }
}

// ============================================================================
// K3: fp16 mma.sync GEMM, CTA tile 128x128, split-K=2.
// 256 threads, 8 warps (2 warp_m x 4 warp_n), warp tile 64x32.
// A: cp.async fp32 (rows padded to 272 B) 3-stage ring; converted each iter
// to a 2-deep fp16 tile ring (rows 144 B). B: cp.async fp16, 3-stage ring.
// Raw fp32 partials to g_Cpart; fixup applies dinv*relu.
// ============================================================================

static constexpr int TILE_M = 128;
static constexpr int TILE_N = 128;
static constexpr int KC     = 64;
static constexpr int STAGES = 3;
static constexpr int K_SPLIT = 2;
static constexpr int K_PER  = N_NODES / K_SPLIT;               // 4096
static constexpr int ITERS  = K_PER / KC;                      // 64
static constexpr int A32_ROWB = 272;                           // 256 + 16 pad
static constexpr int ROWB     = 144;                           // fp16 row pad
static constexpr uint32_t A32_STAGE = TILE_M * A32_ROWB;       // 34816
static constexpr uint32_t B_STAGE   = TILE_N * ROWB;           // 18432
static constexpr uint32_t A16_STAGE = TILE_M * ROWB;           // 18432
static constexpr uint32_t OFF_A32 = 0;
static constexpr uint32_t OFF_B   = STAGES * A32_STAGE;        // 104448
static constexpr uint32_t OFF_A16 = OFF_B + STAGES * B_STAGE;  // 159744
static constexpr uint32_t GEMM_SMEM = OFF_A16 + 2 * A16_STAGE; // 196608
static constexpr int NTHR = 256;

__device__ __forceinline__ uint32_t smem_to_u32(const void* p) {
    uint32_t a;
    asm("{ .reg .u64 t; cvta.to.shared.u64 t, %1; cvt.u32.u64 %0, t; }"
        : "=r"(a) : "l"(p));
    return a;
}

__device__ __forceinline__ uint32_t h2_as_u32(__half2 h) {
    return *reinterpret_cast<uint32_t*>(&h);
}

__device__ __forceinline__ void ldsm_x4(uint32_t r[4], uint32_t addr) {
    asm volatile("ldmatrix.sync.aligned.m8n8.x4.shared.b16 {%0,%1,%2,%3}, [%4];"
                 : "=r"(r[0]), "=r"(r[1]), "=r"(r[2]), "=r"(r[3]) : "r"(addr));
}

__device__ __forceinline__ void mma_f16(float d[4], const uint32_t a[4],
                                        uint32_t b0, uint32_t b1) {
    asm volatile(
        "mma.sync.aligned.m16n8k16.row.col.f32.f16.f16.f32 "
        "{%0,%1,%2,%3}, {%4,%5,%6,%7}, {%8,%9}, {%0,%1,%2,%3};"
        : "+f"(d[0]), "+f"(d[1]), "+f"(d[2]), "+f"(d[3])
        : "r"(a[0]), "r"(a[1]), "r"(a[2]), "r"(a[3]), "r"(b0), "r"(b1));
}

__global__ __launch_bounds__(NTHR, 1) void gcn_gemm(const float* __restrict__ A) {
    extern __shared__ __align__(16) char smem_c[];
    const int tid = threadIdx.x;
    const int lane = tid & 31;
    const int wid = tid >> 5;
    const int warp_m = wid & 1;        // 2 warp rows of 64
    const int warp_n = wid >> 1;       // 4 warp cols of 32
    const int m0 = blockIdx.x * TILE_M;
    const int ks = blockIdx.y;
    const size_t kbase = (size_t)ks * K_PER;
    const uint32_t sbase = smem_to_u32(smem_c);

    // ---- cp.async A plan: 128 rows x 16 chunks = 2048 -> 8 per thread
    // ---- cp.async B plan: 128 rows x 8 chunks = 1024 -> 4 per thread
    uint32_t a_dst[8]; const char* a_srcp[8];
    #pragma unroll
    for (int u = 0; u < 8; u++) {
        int id = tid + u * NTHR;
        int row = id >> 4, c = id & 15;
        a_dst[u] = OFF_A32 + (uint32_t)(row * A32_ROWB + c * 16);
        a_srcp[u] = (const char*)(A + (size_t)(m0 + row) * N_NODES + kbase)
                    + c * 16;
    }
    uint32_t b_dst[4]; const char* b_srcp[4];
    #pragma unroll
    for (int u = 0; u < 4; u++) {
        int id = tid + u * NTHR;
        int row = id >> 3, c = id & 7;
        b_dst[u] = OFF_B + (uint32_t)(row * ROWB + c * 16);
        b_srcp[u] = (const char*)(g_Gh + (size_t)row * N_NODES + kbase) + c * 16;
    }

    auto issue = [&](int j) {
        const uint32_t sa = (uint32_t)(j % STAGES) * A32_STAGE;
        const uint32_t sb = (uint32_t)(j % STAGES) * B_STAGE;
        const size_t ka = (size_t)j * (KC * 4);
        const size_t kb = (size_t)j * (KC * 2);
        #pragma unroll
        for (int u = 0; u < 8; u++)
            asm volatile("cp.async.cg.shared.global [%0], [%1], 16;"
                         :: "r"(sbase + sa + a_dst[u]), "l"(a_srcp[u] + ka)
                         : "memory");
        #pragma unroll
        for (int u = 0; u < 4; u++)
            asm volatile("cp.async.cg.shared.global [%0], [%1], 16;"
                         :: "r"(sbase + sb + b_dst[u]), "l"(b_srcp[u] + kb)
                         : "memory");
    };

    // ---- convert plan: thread -> row = tid&127, half = tid>>7 (32 floats)
    const int c_row = tid & 127;
    const int c_half = tid >> 7;
    const uint32_t c_src = OFF_A32 + (uint32_t)(c_row * A32_ROWB + c_half * 128);
    const uint32_t c_dst = OFF_A16 + (uint32_t)(c_row * ROWB + c_half * 64);

    // ---- prologue: 2 stages in flight
    issue(0); asm volatile("cp.async.commit_group;" ::: "memory");
    issue(1); asm volatile("cp.async.commit_group;" ::: "memory");

    // ---- ldmatrix lane addressing (bytes, within tile)
    const uint32_t a_off = (uint32_t)((warp_m * 64 + (lane & 15)) * ROWB
                                      + ((lane >> 4) * 8) * 2);
    const uint32_t b_off = (uint32_t)((warp_n * 32 + ((lane >> 4) << 3)
                                       + (lane & 7)) * ROWB
                                      + (((lane >> 3) & 1) * 8) * 2);

    float acc[4][4][4];
    #pragma unroll
    for (int mf = 0; mf < 4; mf++)
        #pragma unroll
        for (int nf = 0; nf < 4; nf++)
            #pragma unroll
            for (int q = 0; q < 4; q++) acc[mf][nf][q] = 0.f;

    for (int i = 0; i < ITERS; i++) {
        asm volatile("cp.async.wait_group 1;" ::: "memory");
        __syncthreads();   // stage i (A32 + B) resident; prev A16 readers done

        // convert A32[i%3] -> A16[i%2]
        {
            const char* src = smem_c + c_src + (uint32_t)(i % STAGES) * A32_STAGE;
            char* dst = smem_c + c_dst + (uint32_t)(i & 1) * A16_STAGE;
            #pragma unroll
            for (int q = 0; q < 4; q++) {
                float4 v0 = *reinterpret_cast<const float4*>(src + q * 32);
                float4 v1 = *reinterpret_cast<const float4*>(src + q * 32 + 16);
                uint4 hv;
                hv.x = h2_as_u32(__floats2half2_rn(v0.x, v0.y));
                hv.y = h2_as_u32(__floats2half2_rn(v0.z, v0.w));
                hv.z = h2_as_u32(__floats2half2_rn(v1.x, v1.y));
                hv.w = h2_as_u32(__floats2half2_rn(v1.z, v1.w));
                *reinterpret_cast<uint4*>(dst + q * 16) = hv;
            }
        }

        if (i + 2 < ITERS) issue(i + 2);
        asm volatile("cp.async.commit_group;" ::: "memory");

        __syncthreads();   // A16[i%2] visible

        const uint32_t aA = sbase + OFF_A16 + (uint32_t)(i & 1) * A16_STAGE
                            + a_off;
        const uint32_t aB = sbase + OFF_B + (uint32_t)(i % STAGES) * B_STAGE
                            + b_off;
        #pragma unroll
        for (int kk = 0; kk < KC / 16; kk++) {
            const uint32_t ko = (uint32_t)(kk * 32);
            uint32_t af[4][4], bf[8];
            #pragma unroll
            for (int mf = 0; mf < 4; mf++)
                ldsm_x4(af[mf], aA + (uint32_t)(mf * 16 * ROWB) + ko);
            ldsm_x4(&bf[0], aB + ko);                       // nf 0,1
            ldsm_x4(&bf[4], aB + 16 * ROWB + ko);           // nf 2,3
            #pragma unroll
            for (int mf = 0; mf < 4; mf++) {
                mma_f16(acc[mf][0], af[mf], bf[0], bf[1]);
                mma_f16(acc[mf][1], af[mf], bf[2], bf[3]);
                mma_f16(acc[mf][2], af[mf], bf[4], bf[5]);
                mma_f16(acc[mf][3], af[mf], bf[6], bf[7]);
            }
        }
    }

    // ---- epilogue: raw fp32 partials -> g_Cpart[ks]
    const int qr = lane >> 2;
    const int qc = lane & 3;
    float* Cp = g_Cpart[ks];
    #pragma unroll
    for (int mf = 0; mf < 4; mf++) {
        const int m = m0 + warp_m * 64 + mf * 16 + qr;
        #pragma unroll
        for (int nf = 0; nf < 4; nf++) {
            const int n = warp_n * 32 + nf * 8 + 2 * qc;
            *reinterpret_cast<float2*>(Cp + (size_t)m * D_FEAT + n) =
                make_float2(acc[mf][nf][0], acc[mf][nf][1]);
            *reinterpret_cast<float2*>(Cp + (size_t)(m + 8) * D_FEAT + n) =
                make_float2(acc[mf][nf][2], acc[mf][nf][3]);
        }
    }
}

// ============================================================================
// K4: out[m][o] = relu(dinv[m] * (C0 + C1))
// ============================================================================

__global__ __launch_bounds__(256) void fixup_kernel(float* __restrict__ out) {
    const size_t idx = (size_t)blockIdx.x * 256 + threadIdx.x;  // float4 index
    const float4 c0 = reinterpret_cast<const float4*>(g_Cpart[0])[idx];
    const float4 c1 = reinterpret_cast<const float4*>(g_Cpart[1])[idx];
    const int m = (int)(idx >> 5);          // 32 float4 per 128-wide row
    const float s = g_dinv[m];
    float4 r;
    r.x = fmaxf(s * (c0.x + c1.x), 0.f);
    r.y = fmaxf(s * (c0.y + c1.y), 0.f);
    r.z = fmaxf(s * (c0.z + c1.z), 0.f);
    r.w = fmaxf(s * (c0.w + c1.w), 0.f);
    reinterpret_cast<float4*>(out)[idx] = r;
}

// ============================================================================
// Launch
// ============================================================================

extern "C" void kernel_launch(void* const* d_in, const int* in_sizes, int n_in,
                              void* d_out, int out_size) {
    const float* A = (const float*)d_in[0];
    const float* X = (const float*)d_in[1];
    const float* W = (const float*)d_in[2];
    for (int i = 0; i < n_in; i++) {
        if (in_sizes[i] == N_NODES * N_NODES)      A = (const float*)d_in[i];
        else if (in_sizes[i] == N_NODES * D_FEAT)  X = (const float*)d_in[i];
        else if (in_sizes[i] == D_FEAT * D_FEAT)   W = (const float*)d_in[i];
    }
    float* out = (float*)d_out;

    cudaFuncSetAttribute(build_gt, cudaFuncAttributeMaxDynamicSharedMemorySize,
                         K2_SMEM);
    cudaFuncSetAttribute(gcn_gemm, cudaFuncAttributeMaxDynamicSharedMemorySize,
                         GEMM_SMEM);

    deg_kernel<<<N_NODES, 128>>>(A);
    build_gt<<<N_NODES / K2_ROWS, 128, K2_SMEM>>>(X, W);
    gcn_gemm<<<dim3(N_NODES / TILE_M, K_SPLIT), NTHR, GEMM_SMEM>>>(A);
    fixup_kernel<<<(N_NODES * D_FEAT / 4) / 256, 256>>>(out);
}